// round 2
// baseline (speedup 1.0000x reference)
#include <cuda_runtime.h>

// Problem constants
#define NZ_COLS 512          // DIM_IN
#define MULV    128
#define NZT     64           // z-tile for main kernel
#define WCH     8            // w-slices per CTA in main kernel
#define K2_ZT   32           // z-tile for scalar kernel

// PW constants
#define PW_SS 0.0625f
#define PW_VV 0.03608439182435161f        // 1/(16*sqrt(3))
#define PW_SV 0.0078125f                  // sqrt(3)/128/sqrt(3) = 1/128

// Transposed copy of w_sv: g_wt[w][u][v] = w_sv[u][v][w]   (8.4 MB scratch)
__device__ float g_wt[128 * 128 * 128];

// ---------------------------------------------------------------------------
// Prologue: transpose w_sv[u,v,w] -> g_wt[w,u,v] so per-w slices are [u][v]
// contiguous. For each u we transpose the (v,w) 128x128 matrix.
// ---------------------------------------------------------------------------
__global__ void transpose_wsv_kernel(const float* __restrict__ wsv) {
    __shared__ float tile[32][33];
    const int u  = blockIdx.z;
    const int v0 = blockIdx.y * 32;
    const int w0 = blockIdx.x * 32;
    const float* src = wsv + (size_t)u * 16384;
#pragma unroll
    for (int j = threadIdx.y; j < 32; j += 8)
        tile[j][threadIdx.x] = src[(size_t)(v0 + j) * 128 + (w0 + threadIdx.x)];
    __syncthreads();
#pragma unroll
    for (int j = threadIdx.y; j < 32; j += 8)
        g_wt[(size_t)(w0 + j) * 16384 + (size_t)u * 128 + (v0 + threadIdx.x)] =
            tile[threadIdx.x][j];
}

// ---------------------------------------------------------------------------
// Main kernel: fused  t[z,v,w] = sum_u xs[z,u]*w_sv[u,v,w]
//                     out_v[z,w,i] = PW_SV * sum_v t[z,v,w]*xv[z,v,i]
// CTA: 64 z-rows x 8 consecutive w. 128 threads, 8z x 8v register tile.
// smem: xs tile [64][128] (32KB) + W slice [128][128] (64KB) = 96KB -> 2 CTA/SM
// ---------------------------------------------------------------------------
__global__ __launch_bounds__(128) void sv_main_kernel(
    const float* __restrict__ x, float* __restrict__ out)
{
    extern __shared__ float smem[];
    float* xs_s = smem;              // [64][128]
    float* ws_s = smem + NZT * 128;  // [128][128]  (u-major, v contiguous)

    const int tid = threadIdx.x;
    const int tx  = tid & 15;        // v-group  (16 groups of 8 v)
    const int ty  = tid >> 4;        // z-group  (8 groups of 8 z)
    const int z0    = blockIdx.x * NZT;
    const int wbase = blockIdx.y * WCH;

    // Load xs tile (coalesced float4)
    for (int i = tid; i < NZT * 128 / 4; i += 128) {
        int r = i >> 5;              // z row within tile
        int c = (i & 31) << 2;       // column
        *(float4*)(xs_s + r * 128 + c) =
            *(const float4*)(x + (size_t)(z0 + r) * NZ_COLS + c);
    }

    const int zb = ty * 8;
    const int vb = tx * 8;

    for (int wi = 0; wi < WCH; ++wi) {
        const int w = wbase + wi;
        __syncthreads();             // prev-iter smem reads done / xs load done
        {
            const float* wt = g_wt + (size_t)w * 16384;
            for (int i = tid; i < 16384 / 4; i += 128)
                *(float4*)(ws_s + i * 4) = *(const float4*)(wt + i * 4);
        }
        __syncthreads();

        // GEMM: acc[j][k] = t[z0+zb+j, vb+k] for this w
        float acc[8][8];
#pragma unroll
        for (int j = 0; j < 8; ++j)
#pragma unroll
            for (int k = 0; k < 8; ++k) acc[j][k] = 0.f;

#pragma unroll 8
        for (int u = 0; u < 128; ++u) {
            float4 b0 = *(const float4*)(ws_s + u * 128 + vb);
            float4 b1 = *(const float4*)(ws_s + u * 128 + vb + 4);
            float bb[8] = {b0.x, b0.y, b0.z, b0.w, b1.x, b1.y, b1.z, b1.w};
#pragma unroll
            for (int j = 0; j < 8; ++j) {
                float a = xs_s[(zb + j) * 128 + u];
#pragma unroll
                for (int k = 0; k < 8; ++k) acc[j][k] += a * bb[k];
            }
        }

        // Epilogue: reduce over v with xv, then across the 16 v-lanes.
#pragma unroll
        for (int j = 0; j < 8; ++j) {
            const int z = z0 + zb + j;
            // xv[z, vb..vb+7, 0..2] = 24 consecutive floats (aligned)
            const float4* pv =
                (const float4*)(x + (size_t)z * NZ_COLS + MULV + vb * 3);
            float4 q0 = pv[0], q1 = pv[1], q2 = pv[2];
            float4 q3 = pv[3], q4 = pv[4], q5 = pv[5];
            float vv[24] = {q0.x, q0.y, q0.z, q0.w, q1.x, q1.y, q1.z, q1.w,
                            q2.x, q2.y, q2.z, q2.w, q3.x, q3.y, q3.z, q3.w,
                            q4.x, q4.y, q4.z, q4.w, q5.x, q5.y, q5.z, q5.w};
            float o0 = 0.f, o1 = 0.f, o2 = 0.f;
#pragma unroll
            for (int k = 0; k < 8; ++k) {
                o0 += acc[j][k] * vv[k * 3 + 0];
                o1 += acc[j][k] * vv[k * 3 + 1];
                o2 += acc[j][k] * vv[k * 3 + 2];
            }
            // butterfly over tx (lane bits 0..3): full sum lands in all lanes
#pragma unroll
            for (int m = 8; m >= 1; m >>= 1) {
                o0 += __shfl_xor_sync(0xffffffffu, o0, m);
                o1 += __shfl_xor_sync(0xffffffffu, o1, m);
                o2 += __shfl_xor_sync(0xffffffffu, o2, m);
            }
            if (tx == 0) {
                float* po = out + (size_t)z * NZ_COLS + MULV + w * 3;
                po[0] = PW_SV * o0;
                po[1] = PW_SV * o1;
                po[2] = PW_SV * o2;
            }
        }
    }
}

// ---------------------------------------------------------------------------
// Scalar kernel: out_s[z,u] = PW_SS*xs[z,u]*(w_ss @ xs[z])_u
//                           + PW_VV*sum_i xv[z,u,i]*(w_vv @ xv[z,:,i])_u
// CTA: 32 z rows, all 128 u. 512 threads, thread tile 2z x 4u.
// smem: x tile [32][512] (64KB) + transposed weights 2x[128][132] (135KB)
// ---------------------------------------------------------------------------
__global__ __launch_bounds__(512) void scalar_kernel(
    const float* __restrict__ x, const float* __restrict__ w_ss,
    const float* __restrict__ w_vv, float* __restrict__ out)
{
    extern __shared__ float smem[];
    float* xt   = smem;                    // [32][512]
    float* wsst = smem + K2_ZT * NZ_COLS;  // [128][132]  (v-major, u contiguous)
    float* wvvt = wsst + 128 * 132;        // [128][132]

    const int tid = threadIdx.x;
    const int z0  = blockIdx.x * K2_ZT;

    for (int i = tid; i < K2_ZT * NZ_COLS / 4; i += 512)
        ((float4*)xt)[i] = ((const float4*)(x + (size_t)z0 * NZ_COLS))[i];
    for (int i = tid; i < 16384; i += 512) {
        int r = i >> 7, c = i & 127;       // w[r][c] -> wt[c][r]
        wsst[c * 132 + r] = w_ss[i];
        wvvt[c * 132 + r] = w_vv[i];
    }
    __syncthreads();

    const int tx = tid & 31;               // u-group (32 groups of 4 u)
    const int ty = tid >> 5;               // z-group (16 groups of 2 z)
    const int u  = tx * 4;
    const int zl = ty * 2;

    float ass[2][4], av0[2][4], av1[2][4], av2[2][4];
#pragma unroll
    for (int j = 0; j < 2; ++j)
#pragma unroll
        for (int k = 0; k < 4; ++k) {
            ass[j][k] = 0.f; av0[j][k] = 0.f; av1[j][k] = 0.f; av2[j][k] = 0.f;
        }

#pragma unroll 4
    for (int v = 0; v < 128; ++v) {
        float4 ws4 = *(const float4*)(wsst + v * 132 + u);
        float4 wv4 = *(const float4*)(wvvt + v * 132 + u);
        float wsa[4] = {ws4.x, ws4.y, ws4.z, ws4.w};
        float wva[4] = {wv4.x, wv4.y, wv4.z, wv4.w};
#pragma unroll
        for (int jz = 0; jz < 2; ++jz) {
            const float* row = xt + (zl + jz) * NZ_COLS;
            float xsv = row[v];
            float a0 = row[MULV + v * 3 + 0];
            float a1 = row[MULV + v * 3 + 1];
            float a2 = row[MULV + v * 3 + 2];
#pragma unroll
            for (int k = 0; k < 4; ++k) {
                ass[jz][k] += wsa[k] * xsv;
                av0[jz][k] += wva[k] * a0;
                av1[jz][k] += wva[k] * a1;
                av2[jz][k] += wva[k] * a2;
            }
        }
    }

#pragma unroll
    for (int jz = 0; jz < 2; ++jz) {
        const int z = z0 + zl + jz;
        const float* row = xt + (zl + jz) * NZ_COLS;
        float res[4];
#pragma unroll
        for (int k = 0; k < 4; ++k) {
            int uu = u + k;
            float xsu = row[uu];
            float b0 = row[MULV + uu * 3 + 0];
            float b1 = row[MULV + uu * 3 + 1];
            float b2 = row[MULV + uu * 3 + 2];
            res[k] = PW_SS * xsu * ass[jz][k] +
                     PW_VV * (b0 * av0[jz][k] + b1 * av1[jz][k] + b2 * av2[jz][k]);
        }
        float4 r4 = {res[0], res[1], res[2], res[3]};
        *(float4*)(out + (size_t)z * NZ_COLS + u) = r4;
    }
}

// ---------------------------------------------------------------------------
extern "C" void kernel_launch(void* const* d_in, const int* in_sizes, int n_in,
                              void* d_out, int out_size)
{
    const float* x    = (const float*)d_in[0];
    const float* w_ss = (const float*)d_in[1];
    const float* w_sv = (const float*)d_in[2];
    const float* w_vv = (const float*)d_in[3];
    float* out = (float*)d_out;

    const int n = in_sizes[0] / NZ_COLS;   // 8192

    const int main_smem = (NZT * 128 + 128 * 128) * 4;          // 96 KB
    const int k2_smem   = (K2_ZT * NZ_COLS + 2 * 128 * 132) * 4; // ~196 KB

    cudaFuncSetAttribute(sv_main_kernel,
                         cudaFuncAttributeMaxDynamicSharedMemorySize, main_smem);
    cudaFuncSetAttribute(scalar_kernel,
                         cudaFuncAttributeMaxDynamicSharedMemorySize, k2_smem);

    transpose_wsv_kernel<<<dim3(4, 4, 128), dim3(32, 8)>>>(w_sv);
    scalar_kernel<<<n / K2_ZT, 512, k2_smem>>>(x, w_ss, w_vv, out);
    sv_main_kernel<<<dim3(n / NZT, MULV / WCH), 128, main_smem>>>(x, out);
}

// round 4
// speedup vs baseline: 2.6109x; 2.6109x over previous
#include <cuda_runtime.h>
#include <cuda_bf16.h>
#include <cstdint>

#define MULV    128
#define NZ_COLS 512
#define PW_SS 0.0625f
#define PW_VV 0.03608439182435161f
#define PW_SV 0.0078125f
#define K2_ZT 32

// Packed weights: g_wp[v][hl][w][u] bf16  (8.4 MB)
__device__ unsigned char g_wp[128u * 2u * 128u * 256u];

// ---------------- helpers ----------------
__device__ __forceinline__ uint32_t smem_u32(const void* p) {
    uint32_t a;
    asm("{ .reg .u64 t; cvta.to.shared.u64 t, %1; cvt.u32.u64 %0, t; }" : "=r"(a) : "l"(p));
    return a;
}
__device__ __forceinline__ void ldsm4(uint32_t r[4], uint32_t addr) {
    asm volatile("ldmatrix.sync.aligned.m8n8.x4.shared.b16 {%0,%1,%2,%3}, [%4];"
                 : "=r"(r[0]), "=r"(r[1]), "=r"(r[2]), "=r"(r[3]) : "r"(addr));
}
__device__ __forceinline__ void mma16816(float c[4], const uint32_t a[4],
                                         uint32_t b0, uint32_t b1) {
    asm volatile("mma.sync.aligned.m16n8k16.row.col.f32.bf16.bf16.f32 "
                 "{%0,%1,%2,%3}, {%4,%5,%6,%7}, {%8,%9}, {%0,%1,%2,%3};"
                 : "+f"(c[0]), "+f"(c[1]), "+f"(c[2]), "+f"(c[3])
                 : "r"(a[0]), "r"(a[1]), "r"(a[2]), "r"(a[3]), "r"(b0), "r"(b1));
}
__device__ __forceinline__ void cp16(uint32_t sdst, const void* gsrc) {
    asm volatile("cp.async.cg.shared.global [%0], [%1], 16;" :: "r"(sdst), "l"(gsrc));
}
__device__ __forceinline__ void cp_commit() { asm volatile("cp.async.commit_group;"); }
template <int N> __device__ __forceinline__ void cp_wait() {
    asm volatile("cp.async.wait_group %0;" :: "n"(N));
}
__device__ __forceinline__ uint32_t pack_hi_lo(float f, uint32_t& lo_out) {
    __nv_bfloat16 h = __float2bfloat16(f);
    __nv_bfloat16 l = __float2bfloat16(f - __bfloat162float(h));
    lo_out = (uint32_t)__bfloat16_as_ushort(l);
    return (uint32_t)__bfloat16_as_ushort(h);
}

// ---------------------------------------------------------------------------
// Pack w_sv[u][v][w] -> g_wp[v][hl][w][u] bf16. One block per v.
// ---------------------------------------------------------------------------
__global__ void pack_b_kernel(const float* __restrict__ wsv) {
    extern __shared__ float tile[];              // [128 w][133]
    const int v = blockIdx.x;
    const int tid = threadIdx.x;
    for (int idx = tid; idx < 16384; idx += 256) {
        const int u = idx >> 7, w = idx & 127;
        tile[w * 133 + u] = wsv[(size_t)u * 16384 + (size_t)v * 128 + w];
    }
    __syncthreads();
    for (int j = tid; j < 8192; j += 256) {
        const int w = j >> 6, u0 = (j & 63) * 2;
        uint32_t l0, l1;
        uint32_t h0 = pack_hi_lo(tile[w * 133 + u0], l0);
        uint32_t h1 = pack_hi_lo(tile[w * 133 + u0 + 1], l1);
        uint32_t* dhi = (uint32_t*)(g_wp + (((size_t)v * 2 + 0) * 128 + w) * 256);
        uint32_t* dlo = (uint32_t*)(g_wp + (((size_t)v * 2 + 1) * 128 + w) * 256);
        dhi[u0 >> 1] = h0 | (h1 << 16);
        dlo[u0 >> 1] = l0 | (l1 << 16);
    }
}

// ---------------------------------------------------------------------------
// Main fused kernel: grid (64 z-tiles, 2 w-halves), 256 threads (8 warps).
// CTA tile: M=128 z, N=64 w; warp tile m32 x n32 (4M x 2N).
// Loop v=0..127: T_v = Xs_tile @ W[:,v,whalf] (3-pass split-bf16 mma.sync),
//                out_i[z,w] += T_v[z,w] * xv[z,v,i].
// SMEM (bytes): A hi [128][272] @0, A lo @34816, Bbuf0 @69632, Bbuf1 @104448
//   each B buf: hi rows 0-63, lo rows 64-127, stride 272.
// ---------------------------------------------------------------------------
#define A_LO   34816u
#define B_BUF0 69632u
#define B_BUF1 104448u
#define B_LO   17408u
#define SMEM_MAIN 139264

__global__ __launch_bounds__(256, 1) void sv_mma_kernel(
    const float* __restrict__ x, float* __restrict__ out)
{
    extern __shared__ unsigned char smem[];
    const uint32_t sbase = smem_u32(smem);

    const int tid = threadIdx.x;
    const int lane = tid & 31;
    const int warp = tid >> 5;
    const int m0 = (warp >> 1) * 32;     // warp M offset (0,32,64,96)
    const int n0 = (warp & 1) * 32;      // warp N offset (0,32)
    const int z0 = blockIdx.x * 128;
    const int wbase = blockIdx.y * 64;

    // ---- A tile: convert xs rows to bf16 hi/lo in smem ----
    {
        const int row = tid >> 1, uh = (tid & 1) * 64;
        const float4* src = (const float4*)(x + (size_t)(z0 + row) * NZ_COLS + uh);
        uint32_t* dhi = (uint32_t*)(smem + row * 272u + uh * 2u);
        uint32_t* dlo = (uint32_t*)(smem + A_LO + row * 272u + uh * 2u);
#pragma unroll
        for (int j = 0; j < 16; ++j) {
            float4 f = src[j];
            uint32_t l0, l1, l2, l3;
            uint32_t h0 = pack_hi_lo(f.x, l0), h1 = pack_hi_lo(f.y, l1);
            uint32_t h2 = pack_hi_lo(f.z, l2), h3 = pack_hi_lo(f.w, l3);
            dhi[2 * j]     = h0 | (h1 << 16);
            dhi[2 * j + 1] = h2 | (h3 << 16);
            dlo[2 * j]     = l0 | (l1 << 16);
            dlo[2 * j + 1] = l2 | (l3 << 16);
        }
    }

    // per-lane ldmatrix offsets (row-stride 272 B)
    const uint32_t aoff = ((lane & 7) + ((lane >> 3) & 1) * 8) * 272u + ((lane >> 4) & 1) * 16u;
    const uint32_t boff = ((lane & 7) + ((lane >> 4) & 1) * 8) * 272u + ((lane >> 3) & 1) * 16u;

    // B prefetch lambda-ish macro: 32KB per v, 8 x 16B per thread
#define PREFETCH_B(vv, bufaddr) do { \
    const unsigned char* gb = g_wp + (size_t)(vv) * 65536u; \
    _Pragma("unroll") \
    for (int i = 0; i < 8; ++i) { \
        int c = tid + 256 * i; \
        int r = c >> 4;                     /* 0..127: hl = r>>6, wrow = r&63 */ \
        int hl = r >> 6, wrow = r & 63; \
        const void* src = gb + (((size_t)hl * 128) + wbase + wrow) * 256 + (c & 15) * 16; \
        uint32_t dst = (bufaddr) + (uint32_t)(hl * 64 + wrow) * 272u + (c & 15) * 16u; \
        cp16(dst, src); \
    } \
    cp_commit(); \
} while (0)

    PREFETCH_B(0, sbase + B_BUF0);

    float o[3][2][4][4];                 // out accumulators
#pragma unroll
    for (int i = 0; i < 3; ++i)
#pragma unroll
        for (int mi = 0; mi < 2; ++mi)
#pragma unroll
            for (int nf = 0; nf < 4; ++nf)
#pragma unroll
                for (int e = 0; e < 4; ++e) o[i][mi][nf][e] = 0.f;

    const int R0 = m0 + (lane >> 2);     // base z-row for this lane's frags

    for (int v = 0; v < 128; ++v) {
        const uint32_t bufc = sbase + ((v & 1) ? B_BUF1 : B_BUF0);
        if (v < 127) {
            const uint32_t bufn = sbase + (((v + 1) & 1) ? B_BUF1 : B_BUF0);
            PREFETCH_B(v + 1, bufn);
            cp_wait<1>();
        } else {
            cp_wait<0>();
        }
        __syncthreads();

        // hoist xv loads (L1/L2)
        float xr[4][3];
#pragma unroll
        for (int j = 0; j < 4; ++j) {
            const float* p = x + (size_t)(z0 + R0 + 8 * j) * NZ_COLS + MULV + 3 * v;
            xr[j][0] = __ldg(p); xr[j][1] = __ldg(p + 1); xr[j][2] = __ldg(p + 2);
        }

        float c[2][4][4];
#pragma unroll
        for (int mi = 0; mi < 2; ++mi)
#pragma unroll
            for (int nf = 0; nf < 4; ++nf)
#pragma unroll
                for (int e = 0; e < 4; ++e) c[mi][nf][e] = 0.f;

        // 3 passes: (A hi, B hi), (A hi, B lo), (A lo, B hi)
#pragma unroll
        for (int pass = 0; pass < 3; ++pass) {
            const uint32_t abase = sbase + (pass == 2 ? A_LO : 0u);
            const uint32_t bbase = bufc + (pass == 1 ? B_LO : 0u);
#pragma unroll
            for (int k0 = 0; k0 < 128; k0 += 16) {
                uint32_t a0[4], a1[4], b0[4], b1[4];
                ldsm4(a0, abase + (uint32_t)(m0)      * 272u + k0 * 2u + aoff);
                ldsm4(a1, abase + (uint32_t)(m0 + 16) * 272u + k0 * 2u + aoff);
                ldsm4(b0, bbase + (uint32_t)(n0)      * 272u + k0 * 2u + boff);
                ldsm4(b1, bbase + (uint32_t)(n0 + 16) * 272u + k0 * 2u + boff);
                mma16816(c[0][0], a0, b0[0], b0[1]);
                mma16816(c[0][1], a0, b0[2], b0[3]);
                mma16816(c[0][2], a0, b1[0], b1[1]);
                mma16816(c[0][3], a0, b1[2], b1[3]);
                mma16816(c[1][0], a1, b0[0], b0[1]);
                mma16816(c[1][1], a1, b0[2], b0[3]);
                mma16816(c[1][2], a1, b1[0], b1[1]);
                mma16816(c[1][3], a1, b1[2], b1[3]);
            }
        }

        // epilogue: out_i += T * xv
#pragma unroll
        for (int mi = 0; mi < 2; ++mi)
#pragma unroll
            for (int e = 0; e < 4; ++e) {
                const int rj = 2 * mi + (e >> 1);
#pragma unroll
                for (int nf = 0; nf < 4; ++nf) {
                    const float t = c[mi][nf][e];
                    o[0][mi][nf][e] += t * xr[rj][0];
                    o[1][mi][nf][e] += t * xr[rj][1];
                    o[2][mi][nf][e] += t * xr[rj][2];
                }
            }
        __syncthreads();
    }

    // final store: out[z][128 + 3w + i] = PW_SV * o
#pragma unroll
    for (int mi = 0; mi < 2; ++mi)
#pragma unroll
        for (int e = 0; e < 4; ++e) {
            const int row = z0 + R0 + 16 * mi + 8 * (e >> 1);
#pragma unroll
            for (int nf = 0; nf < 4; ++nf) {
                const int w = wbase + n0 + 8 * nf + (lane & 3) * 2 + (e & 1);
                float* p = out + (size_t)row * NZ_COLS + MULV + 3 * w;
                p[0] = PW_SV * o[0][mi][nf][e];
                p[1] = PW_SV * o[1][mi][nf][e];
                p[2] = PW_SV * o[2][mi][nf][e];
            }
        }
}

// ---------------------------------------------------------------------------
// Scalar kernel (unchanged from round 1; ~33 us)
// ---------------------------------------------------------------------------
__global__ __launch_bounds__(512) void scalar_kernel(
    const float* __restrict__ x, const float* __restrict__ w_ss,
    const float* __restrict__ w_vv, float* __restrict__ out)
{
    extern __shared__ float smemf[];
    float* xt   = smemf;
    float* wsst = smemf + K2_ZT * NZ_COLS;
    float* wvvt = wsst + 128 * 132;

    const int tid = threadIdx.x;
    const int z0  = blockIdx.x * K2_ZT;

    for (int i = tid; i < K2_ZT * NZ_COLS / 4; i += 512)
        ((float4*)xt)[i] = ((const float4*)(x + (size_t)z0 * NZ_COLS))[i];
    for (int i = tid; i < 16384; i += 512) {
        int r = i >> 7, c = i & 127;
        wsst[c * 132 + r] = w_ss[i];
        wvvt[c * 132 + r] = w_vv[i];
    }
    __syncthreads();

    const int tx = tid & 31, ty = tid >> 5;
    const int u = tx * 4, zl = ty * 2;

    float ass[2][4], av0[2][4], av1[2][4], av2[2][4];
#pragma unroll
    for (int j = 0; j < 2; ++j)
#pragma unroll
        for (int k = 0; k < 4; ++k) { ass[j][k]=0.f; av0[j][k]=0.f; av1[j][k]=0.f; av2[j][k]=0.f; }

#pragma unroll 4
    for (int v = 0; v < 128; ++v) {
        float4 ws4 = *(const float4*)(wsst + v * 132 + u);
        float4 wv4 = *(const float4*)(wvvt + v * 132 + u);
        float wsa[4] = {ws4.x, ws4.y, ws4.z, ws4.w};
        float wva[4] = {wv4.x, wv4.y, wv4.z, wv4.w};
#pragma unroll
        for (int jz = 0; jz < 2; ++jz) {
            const float* row = xt + (zl + jz) * NZ_COLS;
            float xsv = row[v];
            float a0 = row[MULV + v*3], a1 = row[MULV + v*3 + 1], a2 = row[MULV + v*3 + 2];
#pragma unroll
            for (int k = 0; k < 4; ++k) {
                ass[jz][k] += wsa[k] * xsv;
                av0[jz][k] += wva[k] * a0;
                av1[jz][k] += wva[k] * a1;
                av2[jz][k] += wva[k] * a2;
            }
        }
    }
#pragma unroll
    for (int jz = 0; jz < 2; ++jz) {
        const int z = z0 + zl + jz;
        const float* row = xt + (zl + jz) * NZ_COLS;
        float res[4];
#pragma unroll
        for (int k = 0; k < 4; ++k) {
            int uu = u + k;
            float xsu = row[uu];
            float b0 = row[MULV + uu*3], b1 = row[MULV + uu*3 + 1], b2 = row[MULV + uu*3 + 2];
            res[k] = PW_SS * xsu * ass[jz][k] +
                     PW_VV * (b0 * av0[jz][k] + b1 * av1[jz][k] + b2 * av2[jz][k]);
        }
        float4 r4 = {res[0], res[1], res[2], res[3]};
        *(float4*)(out + (size_t)z * NZ_COLS + u) = r4;
    }
}

// ---------------------------------------------------------------------------
extern "C" void kernel_launch(void* const* d_in, const int* in_sizes, int n_in,
                              void* d_out, int out_size)
{
    const float* x    = (const float*)d_in[0];
    const float* w_ss = (const float*)d_in[1];
    const float* w_sv = (const float*)d_in[2];
    const float* w_vv = (const float*)d_in[3];
    float* out = (float*)d_out;

    const int n = in_sizes[0] / NZ_COLS;           // 8192
    const int pack_smem = 128 * 133 * 4;           // ~68 KB
    const int k2_smem   = (K2_ZT * NZ_COLS + 2 * 128 * 132) * 4;

    cudaFuncSetAttribute(pack_b_kernel, cudaFuncAttributeMaxDynamicSharedMemorySize, pack_smem);
    cudaFuncSetAttribute(sv_mma_kernel, cudaFuncAttributeMaxDynamicSharedMemorySize, SMEM_MAIN);
    cudaFuncSetAttribute(scalar_kernel, cudaFuncAttributeMaxDynamicSharedMemorySize, k2_smem);

    pack_b_kernel<<<128, 256, pack_smem>>>(w_sv);
    scalar_kernel<<<n / K2_ZT, 512, k2_smem>>>(x, w_ss, w_vv, out);
    sv_mma_kernel<<<dim3(n / 128, 2), 256, SMEM_MAIN>>>(x, out);
}

// round 6
// speedup vs baseline: 2.9087x; 1.1141x over previous
#include <cuda_runtime.h>
#include <cuda_bf16.h>
#include <cstdint>

#define MULV    128
#define NZ_COLS 512
#define PW_SS 0.0625f
#define PW_VV 0.03608439182435161f
#define PW_SV 0.0078125f
#define K2_ZT 32

// Packed weights: g_wp[v][hl][w][u] bf16  (8.4 MB)
__device__ unsigned char g_wp[128u * 2u * 128u * 256u];

// ---------------- helpers ----------------
__device__ __forceinline__ uint32_t smem_u32(const void* p) {
    uint32_t a;
    asm("{ .reg .u64 t; cvta.to.shared.u64 t, %1; cvt.u32.u64 %0, t; }" : "=r"(a) : "l"(p));
    return a;
}
__device__ __forceinline__ void ldsm4(uint32_t r[4], uint32_t addr) {
    asm volatile("ldmatrix.sync.aligned.m8n8.x4.shared.b16 {%0,%1,%2,%3}, [%4];"
                 : "=r"(r[0]), "=r"(r[1]), "=r"(r[2]), "=r"(r[3]) : "r"(addr));
}
__device__ __forceinline__ void mma16816(float c[4], const uint32_t a[4],
                                         uint32_t b0, uint32_t b1) {
    asm volatile("mma.sync.aligned.m16n8k16.row.col.f32.bf16.bf16.f32 "
                 "{%0,%1,%2,%3}, {%4,%5,%6,%7}, {%8,%9}, {%0,%1,%2,%3};"
                 : "+f"(c[0]), "+f"(c[1]), "+f"(c[2]), "+f"(c[3])
                 : "r"(a[0]), "r"(a[1]), "r"(a[2]), "r"(a[3]), "r"(b0), "r"(b1));
}
__device__ __forceinline__ void cp16(uint32_t sdst, const void* gsrc) {
    asm volatile("cp.async.cg.shared.global [%0], [%1], 16;" :: "r"(sdst), "l"(gsrc));
}
__device__ __forceinline__ void cp_commit() { asm volatile("cp.async.commit_group;"); }
template <int N> __device__ __forceinline__ void cp_wait() {
    asm volatile("cp.async.wait_group %0;" :: "n"(N));
}
__device__ __forceinline__ uint32_t pack_hi_lo(float f, uint32_t& lo_out) {
    __nv_bfloat16 h = __float2bfloat16(f);
    __nv_bfloat16 l = __float2bfloat16(f - __bfloat162float(h));
    lo_out = (uint32_t)__bfloat16_as_ushort(l);
    return (uint32_t)__bfloat16_as_ushort(h);
}

// ---------------------------------------------------------------------------
// Pack w_sv[u][v][w] -> g_wp[v][hl][w][u] bf16. One block per v.
// ---------------------------------------------------------------------------
__global__ void pack_b_kernel(const float* __restrict__ wsv) {
    extern __shared__ float tile[];              // [128 w][133]
    const int v = blockIdx.x;
    const int tid = threadIdx.x;
    for (int idx = tid; idx < 16384; idx += 256) {
        const int u = idx >> 7, w = idx & 127;
        tile[w * 133 + u] = wsv[(size_t)u * 16384 + (size_t)v * 128 + w];
    }
    __syncthreads();
    for (int j = tid; j < 8192; j += 256) {
        const int w = j >> 6, u0 = (j & 63) * 2;
        uint32_t l0, l1;
        uint32_t h0 = pack_hi_lo(tile[w * 133 + u0], l0);
        uint32_t h1 = pack_hi_lo(tile[w * 133 + u0 + 1], l1);
        uint32_t* dhi = (uint32_t*)(g_wp + (((size_t)v * 2 + 0) * 128 + w) * 256);
        uint32_t* dlo = (uint32_t*)(g_wp + (((size_t)v * 2 + 1) * 128 + w) * 256);
        dhi[u0 >> 1] = h0 | (h1 << 16);
        dlo[u0 >> 1] = l0 | (l1 << 16);
    }
}

// ---------------------------------------------------------------------------
// Main fused kernel: grid (64 z-tiles, 2 w-halves), 256 threads (8 warps).
// CTA tile: M=128 z, N=64 w; warp tile m32 x n32 (4M x 2N).
// Per v: single fused k-loop computing hh+hl+lh split-bf16 products with
// shared ldmatrix loads (8 ldsm4 + 24 mma per k-step), then epilogue
// out_i[z,w] += T_v[z,w] * xv[z,v,i] in registers. One barrier per v.
// SMEM (bytes): A hi [128][272] @0, A lo @34816, Bbuf0 @69632, Bbuf1 @104448
//   each B buf: hi rows 0-63, lo rows 64-127, stride 272.
// ---------------------------------------------------------------------------
#define A_LO   34816u
#define B_BUF0 69632u
#define B_BUF1 104448u
#define B_LO   17408u
#define SMEM_MAIN 139264

__global__ __launch_bounds__(256, 1) void sv_mma_kernel(
    const float* __restrict__ x, float* __restrict__ out)
{
    extern __shared__ unsigned char smem[];
    const uint32_t sbase = smem_u32(smem);

    const int tid = threadIdx.x;
    const int lane = tid & 31;
    const int warp = tid >> 5;
    const int m0 = (warp >> 1) * 32;     // warp M offset (0,32,64,96)
    const int n0 = (warp & 1) * 32;      // warp N offset (0,32)
    const int z0 = blockIdx.x * 128;
    const int wbase = blockIdx.y * 64;

    // ---- A tile: convert xs rows to bf16 hi/lo in smem ----
    {
        const int row = tid >> 1, uh = (tid & 1) * 64;
        const float4* src = (const float4*)(x + (size_t)(z0 + row) * NZ_COLS + uh);
        uint32_t* dhi = (uint32_t*)(smem + row * 272u + uh * 2u);
        uint32_t* dlo = (uint32_t*)(smem + A_LO + row * 272u + uh * 2u);
#pragma unroll
        for (int j = 0; j < 16; ++j) {
            float4 f = src[j];
            uint32_t l0, l1, l2, l3;
            uint32_t h0 = pack_hi_lo(f.x, l0), h1 = pack_hi_lo(f.y, l1);
            uint32_t h2 = pack_hi_lo(f.z, l2), h3 = pack_hi_lo(f.w, l3);
            dhi[2 * j]     = h0 | (h1 << 16);
            dhi[2 * j + 1] = h2 | (h3 << 16);
            dlo[2 * j]     = l0 | (l1 << 16);
            dlo[2 * j + 1] = l2 | (l3 << 16);
        }
    }

    // per-lane ldmatrix offsets (row-stride 272 B)
    const uint32_t aoff = ((lane & 7) + ((lane >> 3) & 1) * 8) * 272u + ((lane >> 4) & 1) * 16u;
    const uint32_t boff = ((lane & 7) + ((lane >> 4) & 1) * 8) * 272u + ((lane >> 3) & 1) * 16u;

    // B prefetch: 32KB per v, 8 x 16B per thread
#define PREFETCH_B(vv, bufaddr) do { \
    const unsigned char* gb = g_wp + (size_t)(vv) * 65536u; \
    _Pragma("unroll") \
    for (int i = 0; i < 8; ++i) { \
        int c = tid + 256 * i; \
        int r = c >> 4;                     /* 0..127: hl = r>>6, wrow = r&63 */ \
        int hl = r >> 6, wrow = r & 63; \
        const void* src = gb + (((size_t)hl * 128) + wbase + wrow) * 256 + (c & 15) * 16; \
        uint32_t dst = (bufaddr) + (uint32_t)(hl * 64 + wrow) * 272u + (c & 15) * 16u; \
        cp16(dst, src); \
    } \
    cp_commit(); \
} while (0)

    PREFETCH_B(0, sbase + B_BUF0);

    float o[3][2][4][4];                 // out accumulators
#pragma unroll
    for (int i = 0; i < 3; ++i)
#pragma unroll
        for (int mi = 0; mi < 2; ++mi)
#pragma unroll
            for (int nf = 0; nf < 4; ++nf)
#pragma unroll
                for (int e = 0; e < 4; ++e) o[i][mi][nf][e] = 0.f;

    const int R0 = m0 + (lane >> 2);     // base z-row for this lane's frags

    const uint32_t aH0 = sbase + (uint32_t)m0 * 272u + aoff;
    const uint32_t aH1 = sbase + (uint32_t)(m0 + 16) * 272u + aoff;
    const uint32_t aL0 = sbase + A_LO + (uint32_t)m0 * 272u + aoff;
    const uint32_t aL1 = sbase + A_LO + (uint32_t)(m0 + 16) * 272u + aoff;

    for (int v = 0; v < 128; ++v) {
        const uint32_t bufc = sbase + ((v & 1) ? B_BUF1 : B_BUF0);
        cp_wait<0>();                    // data for this v resident
        __syncthreads();                 // all warps done reading other buffer
        if (v < 127) {
            const uint32_t bufn = sbase + (((v + 1) & 1) ? B_BUF1 : B_BUF0);
            PREFETCH_B(v + 1, bufn);     // overlaps with the MMA phase below
        }

        // hoist xv loads (L1/L2)
        float xr[4][3];
#pragma unroll
        for (int j = 0; j < 4; ++j) {
            const float* p = x + (size_t)(z0 + R0 + 8 * j) * NZ_COLS + MULV + 3 * v;
            xr[j][0] = __ldg(p); xr[j][1] = __ldg(p + 1); xr[j][2] = __ldg(p + 2);
        }

        float c[2][4][4];
#pragma unroll
        for (int mi = 0; mi < 2; ++mi)
#pragma unroll
            for (int nf = 0; nf < 4; ++nf)
#pragma unroll
                for (int e = 0; e < 4; ++e) c[mi][nf][e] = 0.f;

        const uint32_t bH0 = bufc + (uint32_t)n0 * 272u + boff;
        const uint32_t bH1 = bufc + (uint32_t)(n0 + 16) * 272u + boff;
        const uint32_t bL0 = bufc + B_LO + (uint32_t)n0 * 272u + boff;
        const uint32_t bL1 = bufc + B_LO + (uint32_t)(n0 + 16) * 272u + boff;

        // Fused split-bf16 k-loop: hh + hl + lh with shared fragment loads.
#pragma unroll
        for (int k0 = 0; k0 < 128; k0 += 16) {
            const uint32_t ko = (uint32_t)k0 * 2u;
            uint32_t ah0[4], ah1[4], al0[4], al1[4];
            uint32_t bh0[4], bh1[4], bl0[4], bl1[4];
            ldsm4(ah0, aH0 + ko);
            ldsm4(ah1, aH1 + ko);
            ldsm4(bh0, bH0 + ko);
            ldsm4(bh1, bH1 + ko);
            ldsm4(al0, aL0 + ko);
            ldsm4(al1, aL1 + ko);
            ldsm4(bl0, bL0 + ko);
            ldsm4(bl1, bL1 + ko);
            // hh block
            mma16816(c[0][0], ah0, bh0[0], bh0[1]);
            mma16816(c[0][1], ah0, bh0[2], bh0[3]);
            mma16816(c[0][2], ah0, bh1[0], bh1[1]);
            mma16816(c[0][3], ah0, bh1[2], bh1[3]);
            mma16816(c[1][0], ah1, bh0[0], bh0[1]);
            mma16816(c[1][1], ah1, bh0[2], bh0[3]);
            mma16816(c[1][2], ah1, bh1[0], bh1[1]);
            mma16816(c[1][3], ah1, bh1[2], bh1[3]);
            // hl block
            mma16816(c[0][0], ah0, bl0[0], bl0[1]);
            mma16816(c[0][1], ah0, bl0[2], bl0[3]);
            mma16816(c[0][2], ah0, bl1[0], bl1[1]);
            mma16816(c[0][3], ah0, bl1[2], bl1[3]);
            mma16816(c[1][0], ah1, bl0[0], bl0[1]);
            mma16816(c[1][1], ah1, bl0[2], bl0[3]);
            mma16816(c[1][2], ah1, bl1[0], bl1[1]);
            mma16816(c[1][3], ah1, bl1[2], bl1[3]);
            // lh block
            mma16816(c[0][0], al0, bh0[0], bh0[1]);
            mma16816(c[0][1], al0, bh0[2], bh0[3]);
            mma16816(c[0][2], al0, bh1[0], bh1[1]);
            mma16816(c[0][3], al0, bh1[2], bh1[3]);
            mma16816(c[1][0], al1, bh0[0], bh0[1]);
            mma16816(c[1][1], al1, bh0[2], bh0[3]);
            mma16816(c[1][2], al1, bh1[0], bh1[1]);
            mma16816(c[1][3], al1, bh1[2], bh1[3]);
        }

        // epilogue: out_i += T * xv
#pragma unroll
        for (int mi = 0; mi < 2; ++mi)
#pragma unroll
            for (int e = 0; e < 4; ++e) {
                const int rj = 2 * mi + (e >> 1);
#pragma unroll
                for (int nf = 0; nf < 4; ++nf) {
                    const float t = c[mi][nf][e];
                    o[0][mi][nf][e] += t * xr[rj][0];
                    o[1][mi][nf][e] += t * xr[rj][1];
                    o[2][mi][nf][e] += t * xr[rj][2];
                }
            }
    }

    // final store: out[z][128 + 3w + i] = PW_SV * o
#pragma unroll
    for (int mi = 0; mi < 2; ++mi)
#pragma unroll
        for (int e = 0; e < 4; ++e) {
            const int row = z0 + R0 + 16 * mi + 8 * (e >> 1);
#pragma unroll
            for (int nf = 0; nf < 4; ++nf) {
                const int w = wbase + n0 + 8 * nf + (lane & 3) * 2 + (e & 1);
                float* p = out + (size_t)row * NZ_COLS + MULV + 3 * w;
                p[0] = PW_SV * o[0][mi][nf][e];
                p[1] = PW_SV * o[1][mi][nf][e];
                p[2] = PW_SV * o[2][mi][nf][e];
            }
        }
}

// ---------------------------------------------------------------------------
// Scalar kernel (unchanged)
// ---------------------------------------------------------------------------
__global__ __launch_bounds__(512) void scalar_kernel(
    const float* __restrict__ x, const float* __restrict__ w_ss,
    const float* __restrict__ w_vv, float* __restrict__ out)
{
    extern __shared__ float smemf[];
    float* xt   = smemf;
    float* wsst = smemf + K2_ZT * NZ_COLS;
    float* wvvt = wsst + 128 * 132;

    const int tid = threadIdx.x;
    const int z0  = blockIdx.x * K2_ZT;

    for (int i = tid; i < K2_ZT * NZ_COLS / 4; i += 512)
        ((float4*)xt)[i] = ((const float4*)(x + (size_t)z0 * NZ_COLS))[i];
    for (int i = tid; i < 16384; i += 512) {
        int r = i >> 7, c = i & 127;
        wsst[c * 132 + r] = w_ss[i];
        wvvt[c * 132 + r] = w_vv[i];
    }
    __syncthreads();

    const int tx = tid & 31, ty = tid >> 5;
    const int u = tx * 4, zl = ty * 2;

    float ass[2][4], av0[2][4], av1[2][4], av2[2][4];
#pragma unroll
    for (int j = 0; j < 2; ++j)
#pragma unroll
        for (int k = 0; k < 4; ++k) { ass[j][k]=0.f; av0[j][k]=0.f; av1[j][k]=0.f; av2[j][k]=0.f; }

#pragma unroll 4
    for (int v = 0; v < 128; ++v) {
        float4 ws4 = *(const float4*)(wsst + v * 132 + u);
        float4 wv4 = *(const float4*)(wvvt + v * 132 + u);
        float wsa[4] = {ws4.x, ws4.y, ws4.z, ws4.w};
        float wva[4] = {wv4.x, wv4.y, wv4.z, wv4.w};
#pragma unroll
        for (int jz = 0; jz < 2; ++jz) {
            const float* row = xt + (zl + jz) * NZ_COLS;
            float xsv = row[v];
            float a0 = row[MULV + v*3], a1 = row[MULV + v*3 + 1], a2 = row[MULV + v*3 + 2];
#pragma unroll
            for (int k = 0; k < 4; ++k) {
                ass[jz][k] += wsa[k] * xsv;
                av0[jz][k] += wva[k] * a0;
                av1[jz][k] += wva[k] * a1;
                av2[jz][k] += wva[k] * a2;
            }
        }
    }
#pragma unroll
    for (int jz = 0; jz < 2; ++jz) {
        const int z = z0 + zl + jz;
        const float* row = xt + (zl + jz) * NZ_COLS;
        float res[4];
#pragma unroll
        for (int k = 0; k < 4; ++k) {
            int uu = u + k;
            float xsu = row[uu];
            float b0 = row[MULV + uu*3], b1 = row[MULV + uu*3 + 1], b2 = row[MULV + uu*3 + 2];
            res[k] = PW_SS * xsu * ass[jz][k] +
                     PW_VV * (b0 * av0[jz][k] + b1 * av1[jz][k] + b2 * av2[jz][k]);
        }
        float4 r4 = {res[0], res[1], res[2], res[3]};
        *(float4*)(out + (size_t)z * NZ_COLS + u) = r4;
    }
}

// ---------------------------------------------------------------------------
extern "C" void kernel_launch(void* const* d_in, const int* in_sizes, int n_in,
                              void* d_out, int out_size)
{
    const float* x    = (const float*)d_in[0];
    const float* w_ss = (const float*)d_in[1];
    const float* w_sv = (const float*)d_in[2];
    const float* w_vv = (const float*)d_in[3];
    float* out = (float*)d_out;

    const int n = in_sizes[0] / NZ_COLS;           // 8192
    const int pack_smem = 128 * 133 * 4;           // ~68 KB
    const int k2_smem   = (K2_ZT * NZ_COLS + 2 * 128 * 132) * 4;

    cudaFuncSetAttribute(pack_b_kernel, cudaFuncAttributeMaxDynamicSharedMemorySize, pack_smem);
    cudaFuncSetAttribute(sv_mma_kernel, cudaFuncAttributeMaxDynamicSharedMemorySize, SMEM_MAIN);
    cudaFuncSetAttribute(scalar_kernel, cudaFuncAttributeMaxDynamicSharedMemorySize, k2_smem);

    pack_b_kernel<<<128, 256, pack_smem>>>(w_sv);
    scalar_kernel<<<n / K2_ZT, 512, k2_smem>>>(x, w_ss, w_vv, out);
    sv_mma_kernel<<<dim3(n / 128, 2), 256, SMEM_MAIN>>>(x, out);
}

// round 7
// speedup vs baseline: 3.1908x; 1.0970x over previous
#include <cuda_runtime.h>
#include <cuda_bf16.h>
#include <cstdint>

#define MULV    128
#define NZ_COLS 512
#define PW_SS 0.0625f
#define PW_VV 0.03608439182435161f
#define PW_SV 0.0078125f
#define K2_ZT 32

// Transposed tf32-rounded weights: g_wt[v][w][u] fp32 (8.4 MB)
__device__ float g_wt[128 * 128 * 128];

// ---------------- helpers ----------------
__device__ __forceinline__ uint32_t smem_u32(const void* p) {
    uint32_t a;
    asm("{ .reg .u64 t; cvta.to.shared.u64 t, %1; cvt.u32.u64 %0, t; }" : "=r"(a) : "l"(p));
    return a;
}
__device__ __forceinline__ void ldsm4(uint32_t r[4], uint32_t addr) {
    asm volatile("ldmatrix.sync.aligned.m8n8.x4.shared.b16 {%0,%1,%2,%3}, [%4];"
                 : "=r"(r[0]), "=r"(r[1]), "=r"(r[2]), "=r"(r[3]) : "r"(addr));
}
__device__ __forceinline__ void mma_tf32(float c[4], const uint32_t a[4],
                                         uint32_t b0, uint32_t b1) {
    asm volatile("mma.sync.aligned.m16n8k8.row.col.f32.tf32.tf32.f32 "
                 "{%0,%1,%2,%3}, {%4,%5,%6,%7}, {%8,%9}, {%0,%1,%2,%3};"
                 : "+f"(c[0]), "+f"(c[1]), "+f"(c[2]), "+f"(c[3])
                 : "r"(a[0]), "r"(a[1]), "r"(a[2]), "r"(a[3]), "r"(b0), "r"(b1));
}
__device__ __forceinline__ void cp16(uint32_t sdst, const void* gsrc) {
    asm volatile("cp.async.cg.shared.global [%0], [%1], 16;" :: "r"(sdst), "l"(gsrc));
}
__device__ __forceinline__ void cp_commit() { asm volatile("cp.async.commit_group;"); }
template <int N> __device__ __forceinline__ void cp_wait() {
    asm volatile("cp.async.wait_group %0;" :: "n"(N));
}
__device__ __forceinline__ uint32_t tf32r(float f) {
    uint32_t o;
    asm("cvt.rna.tf32.f32 %0, %1;" : "=r"(o) : "f"(f));
    return o;
}

// ---------------------------------------------------------------------------
// Pack: g_wt[v][w][u] = tf32_round(w_sv[u][v][w]). One block per v.
// ---------------------------------------------------------------------------
__global__ void pack_b_kernel(const float* __restrict__ wsv) {
    extern __shared__ float tile[];              // [128 w][129]
    const int v = blockIdx.x;
    const int tid = threadIdx.x;
    for (int idx = tid; idx < 16384; idx += 256) {
        const int u = idx >> 7, w = idx & 127;   // read coalesced in w
        tile[w * 129 + u] = wsv[(size_t)u * 16384 + (size_t)v * 128 + w];
    }
    __syncthreads();
    uint32_t* dst = (uint32_t*)(g_wt + (size_t)v * 16384);
    for (int j = tid; j < 16384; j += 256) {
        const int w = j >> 7, u = j & 127;       // write coalesced in u
        dst[w * 128 + u] = tf32r(tile[w * 129 + u]);
    }
}

// ---------------------------------------------------------------------------
// Main fused kernel: grid (64 z-tiles, 2 w-halves), 256 threads (8 warps).
// CTA tile: M=128 z, N=64 w; warp tile m32 x n32 (4M x 2N).
// Per v: single-pass tf32 GEMM T_v = Xs @ W[:,v,whalf] (16 k8-steps,
// 4 ldsm4 + 8 mma each), then epilogue out_i[z,w] += T_v[z,w]*xv[z,v,i].
// SMEM: A fp32 [128 rows][528B] @0 (67584B),
//       Bbuf0 [64 rows][528B] @67584, Bbuf1 @101376. Total 135168B.
// ---------------------------------------------------------------------------
#define A_STRIDE 528u
#define B_BUF0   67584u
#define B_BUF1   101376u
#define SMEM_MAIN 135168

__global__ __launch_bounds__(256, 1) void sv_mma_kernel(
    const float* __restrict__ x, float* __restrict__ out)
{
    extern __shared__ unsigned char smem[];
    const uint32_t sbase = smem_u32(smem);

    const int tid = threadIdx.x;
    const int lane = tid & 31;
    const int warp = tid >> 5;
    const int m0 = (warp >> 1) * 32;     // warp M offset (0,32,64,96)
    const int n0 = (warp & 1) * 32;      // warp N offset (0,32)
    const int z0 = blockIdx.x * 128;
    const int wbase = blockIdx.y * 64;

    // ---- A tile: xs rows, tf32-rounded fp32, stride 528B ----
    {
        const int row = tid >> 1, uh = (tid & 1) * 64;
        const float4* src = (const float4*)(x + (size_t)(z0 + row) * NZ_COLS + uh);
        uint32_t* dstp = (uint32_t*)(smem + row * A_STRIDE + uh * 4u);
#pragma unroll
        for (int j = 0; j < 16; ++j) {
            float4 f = src[j];
            dstp[4 * j + 0] = tf32r(f.x);
            dstp[4 * j + 1] = tf32r(f.y);
            dstp[4 * j + 2] = tf32r(f.z);
            dstp[4 * j + 3] = tf32r(f.w);
        }
    }

    // per-lane ldmatrix offsets (row-stride 528 B)
    const uint32_t aoff = ((lane & 7) + ((lane >> 3) & 1) * 8) * A_STRIDE + ((lane >> 4) & 1) * 16u;
    const uint32_t boff = ((lane & 7) + ((lane >> 4) & 1) * 8) * A_STRIDE + ((lane >> 3) & 1) * 16u;

    // B prefetch: 32KB per v (64 w-rows x 512B), 8 x 16B per thread
#define PREFETCH_B(vv, bufaddr) do { \
    const unsigned char* gb = (const unsigned char*)g_wt + \
        (((size_t)(vv) * 128 + wbase) * 512); \
    _Pragma("unroll") \
    for (int i = 0; i < 8; ++i) { \
        int c = tid + 256 * i;              /* 0..2047 */ \
        int r = c >> 5, ch = c & 31; \
        cp16((bufaddr) + (uint32_t)r * A_STRIDE + (uint32_t)ch * 16u, \
             gb + (size_t)r * 512 + ch * 16); \
    } \
    cp_commit(); \
} while (0)

    PREFETCH_B(0, sbase + B_BUF0);

    float o[3][2][4][4];                 // out accumulators
#pragma unroll
    for (int i = 0; i < 3; ++i)
#pragma unroll
        for (int mi = 0; mi < 2; ++mi)
#pragma unroll
            for (int nf = 0; nf < 4; ++nf)
#pragma unroll
                for (int e = 0; e < 4; ++e) o[i][mi][nf][e] = 0.f;

    const int R0 = m0 + (lane >> 2);     // base z-row for this lane's frags

    const uint32_t aH0 = sbase + (uint32_t)m0 * A_STRIDE + aoff;
    const uint32_t aH1 = sbase + (uint32_t)(m0 + 16) * A_STRIDE + aoff;

    for (int v = 0; v < 128; ++v) {
        const uint32_t bufc = sbase + ((v & 1) ? B_BUF1 : B_BUF0);
        cp_wait<0>();                    // data for this v resident
        __syncthreads();                 // all warps done reading other buffer
        if (v < 127) {
            const uint32_t bufn = sbase + (((v + 1) & 1) ? B_BUF1 : B_BUF0);
            PREFETCH_B(v + 1, bufn);     // overlaps with the MMA phase below
        }

        // hoist xv loads (L1/L2)
        float xr[4][3];
#pragma unroll
        for (int j = 0; j < 4; ++j) {
            const float* p = x + (size_t)(z0 + R0 + 8 * j) * NZ_COLS + MULV + 3 * v;
            xr[j][0] = __ldg(p); xr[j][1] = __ldg(p + 1); xr[j][2] = __ldg(p + 2);
        }

        float c[2][4][4];
#pragma unroll
        for (int mi = 0; mi < 2; ++mi)
#pragma unroll
            for (int nf = 0; nf < 4; ++nf)
#pragma unroll
                for (int e = 0; e < 4; ++e) c[mi][nf][e] = 0.f;

        const uint32_t bN0 = bufc + (uint32_t)n0 * A_STRIDE + boff;
        const uint32_t bN1 = bufc + (uint32_t)(n0 + 16) * A_STRIDE + boff;

        // Single-pass tf32 k-loop: 16 k8-steps, 4 ldsm4 + 8 mma each.
#pragma unroll
        for (int k0 = 0; k0 < 128; k0 += 8) {
            const uint32_t ko = (uint32_t)k0 * 4u;
            uint32_t a0[4], a1[4], b0[4], b1[4];
            ldsm4(a0, aH0 + ko);
            ldsm4(a1, aH1 + ko);
            ldsm4(b0, bN0 + ko);
            ldsm4(b1, bN1 + ko);
            mma_tf32(c[0][0], a0, b0[0], b0[1]);
            mma_tf32(c[0][1], a0, b0[2], b0[3]);
            mma_tf32(c[0][2], a0, b1[0], b1[1]);
            mma_tf32(c[0][3], a0, b1[2], b1[3]);
            mma_tf32(c[1][0], a1, b0[0], b0[1]);
            mma_tf32(c[1][1], a1, b0[2], b0[3]);
            mma_tf32(c[1][2], a1, b1[0], b1[1]);
            mma_tf32(c[1][3], a1, b1[2], b1[3]);
        }

        // epilogue: out_i += T * xv
#pragma unroll
        for (int mi = 0; mi < 2; ++mi)
#pragma unroll
            for (int e = 0; e < 4; ++e) {
                const int rj = 2 * mi + (e >> 1);
#pragma unroll
                for (int nf = 0; nf < 4; ++nf) {
                    const float t = c[mi][nf][e];
                    o[0][mi][nf][e] += t * xr[rj][0];
                    o[1][mi][nf][e] += t * xr[rj][1];
                    o[2][mi][nf][e] += t * xr[rj][2];
                }
            }
    }

    // final store: out[z][128 + 3w + i] = PW_SV * o
#pragma unroll
    for (int mi = 0; mi < 2; ++mi)
#pragma unroll
        for (int e = 0; e < 4; ++e) {
            const int row = z0 + R0 + 16 * mi + 8 * (e >> 1);
#pragma unroll
            for (int nf = 0; nf < 4; ++nf) {
                const int w = wbase + n0 + 8 * nf + (lane & 3) * 2 + (e & 1);
                float* p = out + (size_t)row * NZ_COLS + MULV + 3 * w;
                p[0] = PW_SV * o[0][mi][nf][e];
                p[1] = PW_SV * o[1][mi][nf][e];
                p[2] = PW_SV * o[2][mi][nf][e];
            }
        }
}

// ---------------------------------------------------------------------------
// Scalar kernel (unchanged)
// ---------------------------------------------------------------------------
__global__ __launch_bounds__(512) void scalar_kernel(
    const float* __restrict__ x, const float* __restrict__ w_ss,
    const float* __restrict__ w_vv, float* __restrict__ out)
{
    extern __shared__ float smemf[];
    float* xt   = smemf;
    float* wsst = smemf + K2_ZT * NZ_COLS;
    float* wvvt = wsst + 128 * 132;

    const int tid = threadIdx.x;
    const int z0  = blockIdx.x * K2_ZT;

    for (int i = tid; i < K2_ZT * NZ_COLS / 4; i += 512)
        ((float4*)xt)[i] = ((const float4*)(x + (size_t)z0 * NZ_COLS))[i];
    for (int i = tid; i < 16384; i += 512) {
        int r = i >> 7, c = i & 127;
        wsst[c * 132 + r] = w_ss[i];
        wvvt[c * 132 + r] = w_vv[i];
    }
    __syncthreads();

    const int tx = tid & 31, ty = tid >> 5;
    const int u = tx * 4, zl = ty * 2;

    float ass[2][4], av0[2][4], av1[2][4], av2[2][4];
#pragma unroll
    for (int j = 0; j < 2; ++j)
#pragma unroll
        for (int k = 0; k < 4; ++k) { ass[j][k]=0.f; av0[j][k]=0.f; av1[j][k]=0.f; av2[j][k]=0.f; }

#pragma unroll 4
    for (int v = 0; v < 128; ++v) {
        float4 ws4 = *(const float4*)(wsst + v * 132 + u);
        float4 wv4 = *(const float4*)(wvvt + v * 132 + u);
        float wsa[4] = {ws4.x, ws4.y, ws4.z, ws4.w};
        float wva[4] = {wv4.x, wv4.y, wv4.z, wv4.w};
#pragma unroll
        for (int jz = 0; jz < 2; ++jz) {
            const float* row = xt + (zl + jz) * NZ_COLS;
            float xsv = row[v];
            float a0 = row[MULV + v*3], a1 = row[MULV + v*3 + 1], a2 = row[MULV + v*3 + 2];
#pragma unroll
            for (int k = 0; k < 4; ++k) {
                ass[jz][k] += wsa[k] * xsv;
                av0[jz][k] += wva[k] * a0;
                av1[jz][k] += wva[k] * a1;
                av2[jz][k] += wva[k] * a2;
            }
        }
    }
#pragma unroll
    for (int jz = 0; jz < 2; ++jz) {
        const int z = z0 + zl + jz;
        const float* row = xt + (zl + jz) * NZ_COLS;
        float res[4];
#pragma unroll
        for (int k = 0; k < 4; ++k) {
            int uu = u + k;
            float xsu = row[uu];
            float b0 = row[MULV + uu*3], b1 = row[MULV + uu*3 + 1], b2 = row[MULV + uu*3 + 2];
            res[k] = PW_SS * xsu * ass[jz][k] +
                     PW_VV * (b0 * av0[jz][k] + b1 * av1[jz][k] + b2 * av2[jz][k]);
        }
        float4 r4 = {res[0], res[1], res[2], res[3]};
        *(float4*)(out + (size_t)z * NZ_COLS + u) = r4;
    }
}

// ---------------------------------------------------------------------------
extern "C" void kernel_launch(void* const* d_in, const int* in_sizes, int n_in,
                              void* d_out, int out_size)
{
    const float* x    = (const float*)d_in[0];
    const float* w_ss = (const float*)d_in[1];
    const float* w_sv = (const float*)d_in[2];
    const float* w_vv = (const float*)d_in[3];
    float* out = (float*)d_out;

    const int n = in_sizes[0] / NZ_COLS;           // 8192
    const int pack_smem = 128 * 129 * 4;           // ~66 KB
    const int k2_smem   = (K2_ZT * NZ_COLS + 2 * 128 * 132) * 4;

    cudaFuncSetAttribute(pack_b_kernel, cudaFuncAttributeMaxDynamicSharedMemorySize, pack_smem);
    cudaFuncSetAttribute(sv_mma_kernel, cudaFuncAttributeMaxDynamicSharedMemorySize, SMEM_MAIN);
    cudaFuncSetAttribute(scalar_kernel, cudaFuncAttributeMaxDynamicSharedMemorySize, k2_smem);

    pack_b_kernel<<<128, 256, pack_smem>>>(w_sv);
    scalar_kernel<<<n / K2_ZT, 512, k2_smem>>>(x, w_ss, w_vv, out);
    sv_mma_kernel<<<dim3(n / 128, 2), 256, SMEM_MAIN>>>(x, out);
}